// round 6
// baseline (speedup 1.0000x reference)
#include <cuda_runtime.h>

// Problem constants
#define NVEC   131072            // B*H*W = 32*64*64
#define CDIM   64
#define KCODES 512
#define PPB    128               // positions per block
#define NBLOCK (NVEC/PPB)        // 1024
#define NTHR   256
#define CHUNK  64                // codes per chunk
#define NCHUNK (KCODES/CHUNK)    // 8
#define TAU    0.03f             // rescue threshold (>> fp32 pipeline error)
#define RCAP   32768

// Output layout (flattened tuple, float32):
// [loss(1)] [quantized(32*64*64*64)] [encoding_indices(131072)] [perplexity(1)] [codes(131072)]
#define QUANT_ELEMS (32*64*64*64)
#define OUT_LOSS  0
#define OUT_QUANT 1
#define OUT_EIDX  (1 + QUANT_ELEMS)
#define OUT_PERP  (OUT_EIDX + NVEC)
#define OUT_CODES (OUT_PERP + 1)

// Device scratch (no allocations allowed)
__device__ float g_ET[CDIM*KCODES];   // transposed codebook: g_ET[c*512 + k]
__device__ float g_ee[KCODES];        // ||e_k||^2
__device__ float g_counts[KCODES];
__device__ float g_loss;
__device__ int   g_rescue_n;
__device__ int   g_rescue_pos[RCAP];
__device__ int   g_rescue_cand[RCAP]; // i1 | (i2<<16)

typedef unsigned long long u64;

__device__ __forceinline__ u64 fma2(u64 a, u64 b, u64 c){
    u64 d; asm("fma.rn.f32x2 %0, %1, %2, %3;" : "=l"(d) : "l"(a), "l"(b), "l"(c)); return d;
}
__device__ __forceinline__ void unpack2(u64 a, float& x, float& y){
    asm("mov.b64 {%0, %1}, %2;" : "=f"(x), "=f"(y) : "l"(a));
}

// ---------------------------------------------------------------------------
// Prep: transpose E, compute ||e||^2, zero accumulators. grid=17 x 256 thr.
// ---------------------------------------------------------------------------
__global__ void vq_prep(const float* __restrict__ emb){
    int blk = blockIdx.x;
    if (blk < 16){
        for (int i = blk*2048 + threadIdx.x; i < (blk+1)*2048; i += NTHR){
            int k = i >> 6, c = i & 63;
            g_ET[c*KCODES + k] = emb[i];
        }
    } else {
        int t = threadIdx.x;
        for (int k = t; k < KCODES; k += NTHR){
            const float4* e4 = (const float4*)(emb + k*CDIM);
            float s = 0.f;
            #pragma unroll
            for (int q = 0; q < 16; q++){
                float4 v = e4[q];
                s = fmaf(v.x, v.x, s); s = fmaf(v.y, v.y, s);
                s = fmaf(v.z, v.z, s); s = fmaf(v.w, v.w, s);
            }
            g_ee[k] = s;
        }
        for (int k = t; k < KCODES; k += NTHR) g_counts[k] = 0.f;
        if (t == 0){ g_loss = 0.f; g_rescue_n = 0; }
    }
}

// ---------------------------------------------------------------------------
// Main kernel: distances + top-2 argmin + provisional outputs.
// f32x2 pairing over POSITIONS (x-pairs load directly from smem); codebook
// values pre-duplicated in smem (e-dup pairs load directly). Zero pack MOVs.
// ---------------------------------------------------------------------------
__global__ void __launch_bounds__(NTHR) vq_main(const float* __restrict__ x,
                                                const float* __restrict__ emb,
                                                float* __restrict__ out){
    extern __shared__ float sm[];
    float* xs   = sm;                   // [64][128]  x tile
    float* es2  = xs + CDIM*PPB;        // [64][128]  duplicated code chunk {e,e}
    float* ees  = es2 + CDIM*CHUNK*2;   // [512]
    float* xxs  = ees + KCODES;         // [128]
    int*   idxs = (int*)(xxs + PPB);    // [128]
    float* lsum = (float*)(idxs + PPB); // [1]

    const int tid = threadIdx.x;
    const int tx = tid & 15;            // code group (4 codes)
    const int ty = tid >> 4;            // position group (8 positions)
    const int pos0 = blockIdx.x * PPB;
    const int b  = pos0 >> 12;
    const int s0 = pos0 & 4095;
    const float* xrow = x + (size_t)b*262144 + s0;

    #pragma unroll
    for (int i4 = tid; i4 < CDIM*PPB/4; i4 += NTHR){
        int c = i4 >> 5, j4 = i4 & 31;
        ((float4*)xs)[i4] = *(const float4*)(xrow + c*4096 + j4*4);
    }
    for (int i = tid; i < KCODES; i += NTHR) ees[i] = g_ee[i];
    if (tid == 0) *lsum = 0.f;
    __syncthreads();

    if (tid < PPB){
        float s = 0.f;
        #pragma unroll 16
        for (int k = 0; k < CDIM; k++){ float v = xs[k*PPB + tid]; s = fmaf(v, v, s); }
        xxs[tid] = s;
    }

    float bv1[8], bv2[8]; int bi1[8], bi2[8];
    #pragma unroll
    for (int u = 0; u < 8; u++){ bv1[u] = 3.4e38f; bi1[u] = 0; bv2[u] = 3.4e38f; bi2[u] = 0; }

    for (int ch = 0; ch < NCHUNK; ch++){
        // Fill duplicated code chunk: es2[c][2*q4+{0..7}] = {v.x,v.x,v.y,v.y},{v.z,v.z,v.w,v.w}
        for (int i4 = tid; i4 < CDIM*CHUNK/4; i4 += NTHR){
            int c = i4 >> 4, q = i4 & 15;
            float4 v = *(const float4*)(g_ET + c*KCODES + ch*CHUNK + q*4);
            float4* dst = (float4*)(es2 + c*(2*CHUNK) + q*8);
            dst[0] = make_float4(v.x, v.x, v.y, v.y);
            dst[1] = make_float4(v.z, v.z, v.w, v.w);
        }
        __syncthreads();

        u64 acc[4][4];   // [pos-pair][code]
        #pragma unroll
        for (int p = 0; p < 4; p++)
            #pragma unroll
            for (int c = 0; c < 4; c++) acc[p][c] = 0ull;

        #pragma unroll 8
        for (int k = 0; k < CDIM; k++){
            ulonglong2 xA = *(const ulonglong2*)&xs[k*PPB + ty*8];        // pos pairs 0,1
            ulonglong2 xB = *(const ulonglong2*)&xs[k*PPB + ty*8 + 4];    // pos pairs 2,3
            ulonglong2 eA = *(const ulonglong2*)&es2[k*(2*CHUNK) + tx*8]; // codes 0,1 dup
            ulonglong2 eB = *(const ulonglong2*)&es2[k*(2*CHUNK) + tx*8 + 4]; // codes 2,3 dup
            acc[0][0] = fma2(xA.x, eA.x, acc[0][0]);
            acc[0][1] = fma2(xA.x, eA.y, acc[0][1]);
            acc[0][2] = fma2(xA.x, eB.x, acc[0][2]);
            acc[0][3] = fma2(xA.x, eB.y, acc[0][3]);
            acc[1][0] = fma2(xA.y, eA.x, acc[1][0]);
            acc[1][1] = fma2(xA.y, eA.y, acc[1][1]);
            acc[1][2] = fma2(xA.y, eB.x, acc[1][2]);
            acc[1][3] = fma2(xA.y, eB.y, acc[1][3]);
            acc[2][0] = fma2(xB.x, eA.x, acc[2][0]);
            acc[2][1] = fma2(xB.x, eA.y, acc[2][1]);
            acc[2][2] = fma2(xB.x, eB.x, acc[2][2]);
            acc[2][3] = fma2(xB.x, eB.y, acc[2][3]);
            acc[3][0] = fma2(xB.y, eA.x, acc[3][0]);
            acc[3][1] = fma2(xB.y, eA.y, acc[3][1]);
            acc[3][2] = fma2(xB.y, eB.x, acc[3][2]);
            acc[3][3] = fma2(xB.y, eB.y, acc[3][3]);
        }

        // Fold into per-thread top-2. score = ||e||^2 - 2 x.e
        // Codes scanned ascending; strict < keeps first index (jnp tie rule).
        int cb = ch*CHUNK + tx*4;
        #pragma unroll
        for (int c = 0; c < 4; c++){
            float ec = ees[cb + c];
            #pragma unroll
            for (int p = 0; p < 4; p++){
                float dlo, dhi;
                unpack2(acc[p][c], dlo, dhi);
                int u0 = 2*p, u1 = 2*p + 1;
                float s;
                #define VQ_UPD(u, sv) \
                    if (sv < bv1[u]){ bv2[u]=bv1[u]; bi2[u]=bi1[u]; bv1[u]=sv; bi1[u]=cb+c; } \
                    else if (sv < bv2[u]){ bv2[u]=sv; bi2[u]=cb+c; }
                s = fmaf(-2.f, dlo, ec); VQ_UPD(u0, s)
                s = fmaf(-2.f, dhi, ec); VQ_UPD(u1, s)
                #undef VQ_UPD
            }
        }
        __syncthreads();
    }

    // Cross-thread top-2 merge over the 16 tx lanes (bfly stays in half-warp)
    #pragma unroll
    for (int m = 1; m < 16; m <<= 1){
        #pragma unroll
        for (int u = 0; u < 8; u++){
            float ov1 = __shfl_xor_sync(0xffffffffu, bv1[u], m);
            int   oi1 = __shfl_xor_sync(0xffffffffu, bi1[u], m);
            float ov2 = __shfl_xor_sync(0xffffffffu, bv2[u], m);
            int   oi2 = __shfl_xor_sync(0xffffffffu, bi2[u], m);
            if (ov1 < bv1[u] || (ov1 == bv1[u] && oi1 < bi1[u])){
                float nb2; int ni2;
                if (bv1[u] < ov2 || (bv1[u] == ov2 && bi1[u] < oi2)){ nb2 = bv1[u]; ni2 = bi1[u]; }
                else                                                 { nb2 = ov2;    ni2 = oi2;    }
                bv1[u] = ov1; bi1[u] = oi1; bv2[u] = nb2; bi2[u] = ni2;
            } else {
                if (ov1 < bv2[u] || (ov1 == bv2[u] && oi1 < bi2[u])){ bv2[u] = ov1; bi2[u] = oi1; }
            }
        }
    }

    if (tx == 0){
        float ml = 0.f;
        #pragma unroll
        for (int u = 0; u < 8; u++){
            int p = ty*8 + u;
            idxs[p] = bi1[u];
            ml += xxs[p] + bv1[u];
            atomicAdd(&g_counts[bi1[u]], 1.0f);
            if (bv2[u] - bv1[u] < TAU){
                int slot = atomicAdd(&g_rescue_n, 1);
                if (slot < RCAP){
                    g_rescue_pos[slot]  = pos0 + p;
                    g_rescue_cand[slot] = bi1[u] | (bi2[u] << 16);
                }
            }
        }
        atomicAdd(lsum, ml);
    }
    __syncthreads();
    if (tid == 0) atomicAdd(&g_loss, *lsum);

    if (tid < PPB){
        float fi = (float)idxs[tid];
        out[OUT_EIDX  + pos0 + tid] = fi;
        out[OUT_CODES + pos0 + tid] = fi;
    }

    float* q = out + OUT_QUANT + (size_t)b*262144 + s0;
    for (int i = tid; i < CDIM*PPB; i += NTHR){
        int c = i >> 7, j = i & 127;
        q[c*4096 + j] = emb[idxs[j]*CDIM + c];
    }
}

// ---------------------------------------------------------------------------
// Rescue: exact fp64 re-ranking of near-tied top-2 candidates; patch outputs.
// ---------------------------------------------------------------------------
__global__ void vq_rescue(const float* __restrict__ x,
                          const float* __restrict__ emb,
                          float* __restrict__ out){
    int n = g_rescue_n; if (n > RCAP) n = RCAP;
    int lane  = threadIdx.x & 31;
    int warp  = (blockIdx.x * blockDim.x + threadIdx.x) >> 5;
    int nwarp = (gridDim.x * blockDim.x) >> 5;

    for (int e = warp; e < n; e += nwarp){
        int pos = g_rescue_pos[e];
        int pk  = g_rescue_cand[e];
        int i1 = pk & 0xffff, i2 = pk >> 16;
        int b = pos >> 12, s = pos & 4095;
        const float* xp = x + (size_t)b*262144 + s;

        double d1 = 0.0, d2 = 0.0;
        #pragma unroll
        for (int h = 0; h < 2; h++){
            int c = lane + h*32;
            double xv = (double)xp[(size_t)c*4096];
            double t1 = xv - (double)emb[i1*CDIM + c];
            double t2 = xv - (double)emb[i2*CDIM + c];
            d1 = fma(t1, t1, d1);
            d2 = fma(t2, t2, d2);
        }
        #pragma unroll
        for (int m = 16; m; m >>= 1){
            d1 += __shfl_xor_sync(0xffffffffu, d1, m);
            d2 += __shfl_xor_sync(0xffffffffu, d2, m);
        }

        int    lo  = (i1 < i2) ? i1 : i2;
        int    hi  = (i1 < i2) ? i2 : i1;
        double dlo = (i1 < i2) ? d1 : d2;
        double dhi = (i1 < i2) ? d2 : d1;
        int winner = (dhi < dlo) ? hi : lo;

        if (winner != i1){
            if (lane == 0){
                atomicAdd(&g_counts[i1], -1.0f);
                atomicAdd(&g_counts[winner], 1.0f);
                out[OUT_EIDX  + pos] = (float)winner;
                out[OUT_CODES + pos] = (float)winner;
            }
            float* q = out + OUT_QUANT + (size_t)b*262144 + s;
            #pragma unroll
            for (int h = 0; h < 2; h++){
                int c = lane + h*32;
                q[(size_t)c*4096] = emb[winner*CDIM + c];
            }
        }
    }
}

// ---------------------------------------------------------------------------
// Finalize: perplexity + loss scalars. 1 warp, barrier-free.
// ---------------------------------------------------------------------------
__global__ void vq_finalize(float* __restrict__ out){
    int lane = threadIdx.x;
    float s = 0.f;
    #pragma unroll
    for (int q = 0; q < KCODES/32; q++){
        float p = g_counts[q*32 + lane] * (1.0f / (float)NVEC);
        s += p * logf(p + 1e-10f);
    }
    #pragma unroll
    for (int m = 16; m; m >>= 1) s += __shfl_xor_sync(0xffffffffu, s, m);
    if (lane == 0){
        out[OUT_PERP] = expf(-s);
        out[OUT_LOSS] = 0.25f * g_loss * (1.0f / (float)QUANT_ELEMS);
    }
}

// ---------------------------------------------------------------------------
extern "C" void kernel_launch(void* const* d_in, const int* in_sizes, int n_in,
                              void* d_out, int out_size){
    const float* x   = (const float*)d_in[0];   // inputs (32,64,64,64) f32
    const float* emb = (const float*)d_in[1];   // emb_weight (512,64) f32
    float* out = (float*)d_out;

    const int smem_bytes = (CDIM*PPB + CDIM*CHUNK*2 + KCODES + PPB)*4 + PPB*4 + 4;
    cudaFuncSetAttribute(vq_main, cudaFuncAttributeMaxDynamicSharedMemorySize, smem_bytes);

    vq_prep<<<17, NTHR>>>(emb);
    vq_main<<<NBLOCK, NTHR, smem_bytes>>>(x, emb, out);
    vq_rescue<<<64, 256>>>(x, emb, out);
    vq_finalize<<<1, 32>>>(out);
}

// round 8
// speedup vs baseline: 1.3620x; 1.3620x over previous
#include <cuda_runtime.h>

// Problem constants
#define NVEC   131072            // B*H*W = 32*64*64
#define CDIM   64
#define KCODES 512
#define PPB    128               // positions per block
#define NBLOCK (NVEC/PPB)        // 1024
#define NTHR   256
#define CHUNK  64                // codes per chunk
#define NCHUNK (KCODES/CHUNK)    // 8
#define TAU    0.03f             // rescue threshold (>> fp32 pipeline error)
#define RCAP   32768

// Output layout (flattened tuple, float32):
// [loss(1)] [quantized(32*64*64*64)] [encoding_indices(131072)] [perplexity(1)] [codes(131072)]
#define QUANT_ELEMS (32*64*64*64)
#define OUT_LOSS  0
#define OUT_QUANT 1
#define OUT_EIDX  (1 + QUANT_ELEMS)
#define OUT_PERP  (OUT_EIDX + NVEC)
#define OUT_CODES (OUT_PERP + 1)

// Device scratch (no allocations allowed)
__device__ float g_ET[CDIM*KCODES];   // transposed codebook: g_ET[c*512 + k]
__device__ float g_ee[KCODES];        // ||e_k||^2
__device__ float g_counts[KCODES];
__device__ float g_loss;
__device__ int   g_rescue_n;
__device__ int   g_rescue_pos[RCAP];
__device__ int   g_rescue_cand[RCAP]; // i1 | (i2<<16)

typedef unsigned long long u64;

__device__ __forceinline__ u64 fma2(u64 a, u64 b, u64 c){
    u64 d; asm("fma.rn.f32x2 %0, %1, %2, %3;" : "=l"(d) : "l"(a), "l"(b), "l"(c)); return d;
}
__device__ __forceinline__ void unpack2(u64 a, float& x, float& y){
    asm("mov.b64 {%0, %1}, %2;" : "=f"(x), "=f"(y) : "l"(a));
}

// ---------------------------------------------------------------------------
// Prep: transpose E, compute ||e||^2, zero accumulators. grid=17 x 256 thr.
// ---------------------------------------------------------------------------
__global__ void vq_prep(const float* __restrict__ emb){
    int blk = blockIdx.x;
    if (blk < 16){
        for (int i = blk*2048 + threadIdx.x; i < (blk+1)*2048; i += NTHR){
            int k = i >> 6, c = i & 63;
            g_ET[c*KCODES + k] = emb[i];
        }
    } else {
        int t = threadIdx.x;
        for (int k = t; k < KCODES; k += NTHR){
            const float4* e4 = (const float4*)(emb + k*CDIM);
            float s = 0.f;
            #pragma unroll
            for (int q = 0; q < 16; q++){
                float4 v = e4[q];
                s = fmaf(v.x, v.x, s); s = fmaf(v.y, v.y, s);
                s = fmaf(v.z, v.z, s); s = fmaf(v.w, v.w, s);
            }
            g_ee[k] = s;
        }
        for (int k = t; k < KCODES; k += NTHR) g_counts[k] = 0.f;
        if (t == 0){ g_loss = 0.f; g_rescue_n = 0; }
    }
}

// ---------------------------------------------------------------------------
// Main kernel: distances + top-2 argmin + provisional outputs.
// f32x2 pairs over POSITIONS (direct LDS.128 of x), codebook duplicated in
// smem as {e,e} float2s. Thread tx covers codes {tx, tx+16, tx+32, tx+48}:
// each e-load is an 8B LDS at 8B stride across lanes -> conflict-free.
// Inner loop: 2 LDS.128 + 4 LDS.64 + 16 FFMA2, zero MOVs.
// ---------------------------------------------------------------------------
__global__ void __launch_bounds__(NTHR) vq_main(const float* __restrict__ x,
                                                const float* __restrict__ emb,
                                                float* __restrict__ out){
    extern __shared__ float sm[];
    float* xs   = sm;                   // [64][128]  x tile
    float* es2  = xs + CDIM*PPB;        // [64][128]  duplicated code chunk {e,e}
    float* ees  = es2 + CDIM*CHUNK*2;   // [512]
    float* xxs  = ees + KCODES;         // [128]
    int*   idxs = (int*)(xxs + PPB);    // [128]
    float* lsum = (float*)(idxs + PPB); // [1]

    const int tid = threadIdx.x;
    const int tx = tid & 15;            // code lane
    const int ty = tid >> 4;            // position group (8 positions)
    const int pos0 = blockIdx.x * PPB;
    const int b  = pos0 >> 12;
    const int s0 = pos0 & 4095;
    const float* xrow = x + (size_t)b*262144 + s0;

    #pragma unroll
    for (int i4 = tid; i4 < CDIM*PPB/4; i4 += NTHR){
        int c = i4 >> 5, j4 = i4 & 31;
        ((float4*)xs)[i4] = *(const float4*)(xrow + c*4096 + j4*4);
    }
    for (int i = tid; i < KCODES; i += NTHR) ees[i] = g_ee[i];
    if (tid == 0) *lsum = 0.f;
    __syncthreads();

    if (tid < PPB){
        float s = 0.f;
        #pragma unroll 16
        for (int k = 0; k < CDIM; k++){ float v = xs[k*PPB + tid]; s = fmaf(v, v, s); }
        xxs[tid] = s;
    }

    float bv1[8], bv2[8]; int bi1[8], bi2[8];
    #pragma unroll
    for (int u = 0; u < 8; u++){ bv1[u] = 3.4e38f; bi1[u] = 0; bv2[u] = 3.4e38f; bi2[u] = 0; }

    for (int ch = 0; ch < NCHUNK; ch++){
        // Fill duplicated code chunk: es2[c][2j],es2[c][2j+1] = E^T[c][ch*64+j]
        for (int i4 = tid; i4 < CDIM*CHUNK/4; i4 += NTHR){
            int c = i4 >> 4, q = i4 & 15;
            float4 v = *(const float4*)(g_ET + c*KCODES + ch*CHUNK + q*4);
            float4* dst = (float4*)(es2 + c*(2*CHUNK) + q*8);
            dst[0] = make_float4(v.x, v.x, v.y, v.y);
            dst[1] = make_float4(v.z, v.z, v.w, v.w);
        }
        __syncthreads();

        u64 acc[4][4];   // [pos-pair][code-group]
        #pragma unroll
        for (int p = 0; p < 4; p++)
            #pragma unroll
            for (int g = 0; g < 4; g++) acc[p][g] = 0ull;

        const float* xbase = xs + ty*8;
        const float* ebase = es2 + 2*tx;
        #pragma unroll 8
        for (int k = 0; k < CDIM; k++){
            ulonglong2 xA = *(const ulonglong2*)(xbase + k*PPB);        // pos pairs 0,1
            ulonglong2 xB = *(const ulonglong2*)(xbase + k*PPB + 4);    // pos pairs 2,3
            u64 e0 = *(const u64*)(ebase + k*(2*CHUNK));        // code tx    dup
            u64 e1 = *(const u64*)(ebase + k*(2*CHUNK) + 32);   // code tx+16 dup
            u64 e2 = *(const u64*)(ebase + k*(2*CHUNK) + 64);   // code tx+32 dup
            u64 e3 = *(const u64*)(ebase + k*(2*CHUNK) + 96);   // code tx+48 dup
            acc[0][0] = fma2(xA.x, e0, acc[0][0]);
            acc[0][1] = fma2(xA.x, e1, acc[0][1]);
            acc[0][2] = fma2(xA.x, e2, acc[0][2]);
            acc[0][3] = fma2(xA.x, e3, acc[0][3]);
            acc[1][0] = fma2(xA.y, e0, acc[1][0]);
            acc[1][1] = fma2(xA.y, e1, acc[1][1]);
            acc[1][2] = fma2(xA.y, e2, acc[1][2]);
            acc[1][3] = fma2(xA.y, e3, acc[1][3]);
            acc[2][0] = fma2(xB.x, e0, acc[2][0]);
            acc[2][1] = fma2(xB.x, e1, acc[2][1]);
            acc[2][2] = fma2(xB.x, e2, acc[2][2]);
            acc[2][3] = fma2(xB.x, e3, acc[2][3]);
            acc[3][0] = fma2(xB.y, e0, acc[3][0]);
            acc[3][1] = fma2(xB.y, e1, acc[3][1]);
            acc[3][2] = fma2(xB.y, e2, acc[3][2]);
            acc[3][3] = fma2(xB.y, e3, acc[3][3]);
        }

        // Fold into per-thread top-2. score = ||e||^2 - 2 x.e
        // Code index for group g: cb + tx + 16*g -> ascending in g, so strict <
        // keeps the first (lowest) index, matching jnp.argmin tie rule.
        int cb = ch*CHUNK + tx;
        #pragma unroll
        for (int g = 0; g < 4; g++){
            int id = cb + 16*g;
            float ec = ees[id];
            #pragma unroll
            for (int p = 0; p < 4; p++){
                float dlo, dhi;
                unpack2(acc[p][g], dlo, dhi);
                int u0 = 2*p, u1 = 2*p + 1;
                float s;
                #define VQ_UPD(u, sv) \
                    if (sv < bv1[u]){ bv2[u]=bv1[u]; bi2[u]=bi1[u]; bv1[u]=sv; bi1[u]=id; } \
                    else if (sv < bv2[u]){ bv2[u]=sv; bi2[u]=id; }
                s = fmaf(-2.f, dlo, ec); VQ_UPD(u0, s)
                s = fmaf(-2.f, dhi, ec); VQ_UPD(u1, s)
                #undef VQ_UPD
            }
        }
        __syncthreads();
    }

    // Cross-thread top-2 merge over the 16 tx lanes (bfly stays in half-warp)
    #pragma unroll
    for (int m = 1; m < 16; m <<= 1){
        #pragma unroll
        for (int u = 0; u < 8; u++){
            float ov1 = __shfl_xor_sync(0xffffffffu, bv1[u], m);
            int   oi1 = __shfl_xor_sync(0xffffffffu, bi1[u], m);
            float ov2 = __shfl_xor_sync(0xffffffffu, bv2[u], m);
            int   oi2 = __shfl_xor_sync(0xffffffffu, bi2[u], m);
            if (ov1 < bv1[u] || (ov1 == bv1[u] && oi1 < bi1[u])){
                float nb2; int ni2;
                if (bv1[u] < ov2 || (bv1[u] == ov2 && bi1[u] < oi2)){ nb2 = bv1[u]; ni2 = bi1[u]; }
                else                                                 { nb2 = ov2;    ni2 = oi2;    }
                bv1[u] = ov1; bi1[u] = oi1; bv2[u] = nb2; bi2[u] = ni2;
            } else {
                if (ov1 < bv2[u] || (ov1 == bv2[u] && oi1 < bi2[u])){ bv2[u] = ov1; bi2[u] = oi1; }
            }
        }
    }

    if (tx == 0){
        float ml = 0.f;
        #pragma unroll
        for (int u = 0; u < 8; u++){
            int p = ty*8 + u;
            idxs[p] = bi1[u];
            ml += xxs[p] + bv1[u];
            atomicAdd(&g_counts[bi1[u]], 1.0f);
            if (bv2[u] - bv1[u] < TAU){
                int slot = atomicAdd(&g_rescue_n, 1);
                if (slot < RCAP){
                    g_rescue_pos[slot]  = pos0 + p;
                    g_rescue_cand[slot] = bi1[u] | (bi2[u] << 16);
                }
            }
        }
        atomicAdd(lsum, ml);
    }
    __syncthreads();
    if (tid == 0) atomicAdd(&g_loss, *lsum);

    if (tid < PPB){
        float fi = (float)idxs[tid];
        out[OUT_EIDX  + pos0 + tid] = fi;
        out[OUT_CODES + pos0 + tid] = fi;
    }

    float* q = out + OUT_QUANT + (size_t)b*262144 + s0;
    for (int i = tid; i < CDIM*PPB; i += NTHR){
        int c = i >> 7, j = i & 127;
        q[c*4096 + j] = emb[idxs[j]*CDIM + c];
    }
}

// ---------------------------------------------------------------------------
// Rescue: exact fp64 re-ranking of near-tied top-2 candidates; patch outputs.
// ---------------------------------------------------------------------------
__global__ void vq_rescue(const float* __restrict__ x,
                          const float* __restrict__ emb,
                          float* __restrict__ out){
    int n = g_rescue_n; if (n > RCAP) n = RCAP;
    int lane  = threadIdx.x & 31;
    int warp  = (blockIdx.x * blockDim.x + threadIdx.x) >> 5;
    int nwarp = (gridDim.x * blockDim.x) >> 5;

    for (int e = warp; e < n; e += nwarp){
        int pos = g_rescue_pos[e];
        int pk  = g_rescue_cand[e];
        int i1 = pk & 0xffff, i2 = pk >> 16;
        int b = pos >> 12, s = pos & 4095;
        const float* xp = x + (size_t)b*262144 + s;

        double d1 = 0.0, d2 = 0.0;
        #pragma unroll
        for (int h = 0; h < 2; h++){
            int c = lane + h*32;
            double xv = (double)xp[(size_t)c*4096];
            double t1 = xv - (double)emb[i1*CDIM + c];
            double t2 = xv - (double)emb[i2*CDIM + c];
            d1 = fma(t1, t1, d1);
            d2 = fma(t2, t2, d2);
        }
        #pragma unroll
        for (int m = 16; m; m >>= 1){
            d1 += __shfl_xor_sync(0xffffffffu, d1, m);
            d2 += __shfl_xor_sync(0xffffffffu, d2, m);
        }

        int    lo  = (i1 < i2) ? i1 : i2;
        int    hi  = (i1 < i2) ? i2 : i1;
        double dlo = (i1 < i2) ? d1 : d2;
        double dhi = (i1 < i2) ? d2 : d1;
        int winner = (dhi < dlo) ? hi : lo;

        if (winner != i1){
            if (lane == 0){
                atomicAdd(&g_counts[i1], -1.0f);
                atomicAdd(&g_counts[winner], 1.0f);
                out[OUT_EIDX  + pos] = (float)winner;
                out[OUT_CODES + pos] = (float)winner;
            }
            float* q = out + OUT_QUANT + (size_t)b*262144 + s;
            #pragma unroll
            for (int h = 0; h < 2; h++){
                int c = lane + h*32;
                q[(size_t)c*4096] = emb[winner*CDIM + c];
            }
        }
    }
}

// ---------------------------------------------------------------------------
// Finalize: perplexity + loss scalars. 1 warp, barrier-free.
// ---------------------------------------------------------------------------
__global__ void vq_finalize(float* __restrict__ out){
    int lane = threadIdx.x;
    float s = 0.f;
    #pragma unroll
    for (int q = 0; q < KCODES/32; q++){
        float p = g_counts[q*32 + lane] * (1.0f / (float)NVEC);
        s += p * logf(p + 1e-10f);
    }
    #pragma unroll
    for (int m = 16; m; m >>= 1) s += __shfl_xor_sync(0xffffffffu, s, m);
    if (lane == 0){
        out[OUT_PERP] = expf(-s);
        out[OUT_LOSS] = 0.25f * g_loss * (1.0f / (float)QUANT_ELEMS);
    }
}

// ---------------------------------------------------------------------------
extern "C" void kernel_launch(void* const* d_in, const int* in_sizes, int n_in,
                              void* d_out, int out_size){
    const float* x   = (const float*)d_in[0];   // inputs (32,64,64,64) f32
    const float* emb = (const float*)d_in[1];   // emb_weight (512,64) f32
    float* out = (float*)d_out;

    const int smem_bytes = (CDIM*PPB + CDIM*CHUNK*2 + KCODES + PPB)*4 + PPB*4 + 4;
    cudaFuncSetAttribute(vq_main, cudaFuncAttributeMaxDynamicSharedMemorySize, smem_bytes);

    vq_prep<<<17, NTHR>>>(emb);
    vq_main<<<NBLOCK, NTHR, smem_bytes>>>(x, emb, out);
    vq_rescue<<<64, 256>>>(x, emb, out);
    vq_finalize<<<1, 32>>>(out);
}